// round 4
// baseline (speedup 1.0000x reference)
#include <cuda_runtime.h>

#define NF 128
#define N_NODES 100000

// Scratch: static device globals declared as float4 for guaranteed 16B alignment.
__device__ float4 g_agg4[(size_t)N_NODES * NF / 4];   // 51.2 MB aggregation buffer
__device__ float4 g_h4[(size_t)N_NODES * NF / 4];     // 51.2 MB hidden activations
__device__ __align__(16) float g_cnt[N_NODES];        // in-degree counts
__device__ int g_is64;                                // edge_index dtype flag

// ---------------------------------------------------------------------------
// Detect whether edge_index is int64 or int32. For int64 (little-endian,
// non-negative ids < 2^31) every high 4-byte word is 0. For random int32
// indices that pattern over 64 entries is impossible in practice.
// ---------------------------------------------------------------------------
__global__ void detect_kernel(const int* __restrict__ ei_words) {
    if (threadIdx.x == 0 && blockIdx.x == 0) {
        int is64 = 1;
        #pragma unroll
        for (int k = 0; k < 64; k++)
            if (ei_words[2 * k + 1] != 0) { is64 = 0; break; }
        g_is64 = is64;
    }
}

// ---------------------------------------------------------------------------
// Zero the aggregation buffer (and optionally the counts) with float4 stores.
// ---------------------------------------------------------------------------
__global__ void zero_kernel(int n4, int zero_cnt) {
    int i = blockIdx.x * blockDim.x + threadIdx.x;
    float4 z = make_float4(0.f, 0.f, 0.f, 0.f);
    if (i < n4) g_agg4[i] = z;
    if (zero_cnt && i < N_NODES / 4)
        reinterpret_cast<float4*>(g_cnt)[i] = z;
}

// ---------------------------------------------------------------------------
// Edge scatter: one warp per edge. Gather the 512B source row (one LDG.128
// per lane, coalesced) and reduce into agg[dst] with a single vector
// reduction per lane (red.global.add.v4.f32) -> 4x fewer atomic instructions
// than scalar atomicAdd. Lane 0 counts in-degree (layer 1 only).
// Edge indices read as int64 or int32 per the detected flag.
// ---------------------------------------------------------------------------
__global__ void scatter_kernel(const float* __restrict__ feat,
                               const void* __restrict__ ei,
                               int E, int do_count, int use_h) {
    const float* f = use_h ? reinterpret_cast<const float*>(g_h4) : feat;
    int gw = (blockIdx.x * blockDim.x + threadIdx.x) >> 5;
    int lane = threadIdx.x & 31;
    if (gw >= E) return;
    int s, d;
    if (g_is64) {
        const long long* e = (const long long*)ei;
        s = (int)e[gw]; d = (int)e[E + gw];
    } else {
        const int* e = (const int*)ei;
        s = e[gw]; d = e[E + gw];
    }
    s = min(max(s, 0), N_NODES - 1);   // defensive clamp (no-op on valid data)
    d = min(max(d, 0), N_NODES - 1);
    float4 v = reinterpret_cast<const float4*>(f + (size_t)s * NF)[lane];
    float* dp = reinterpret_cast<float*>(g_agg4) + (size_t)d * NF + lane * 4;
    asm volatile("red.global.add.v4.f32 [%0], {%1, %2, %3, %4};"
                 :: "l"(dp), "f"(v.x), "f"(v.y), "f"(v.z), "f"(v.w)
                 : "memory");
    if (do_count && lane == 0) atomicAdd(g_cnt + d, 1.0f);
}

// Packed fp32x2 FMA (Blackwell): 2x the throughput of 3-reg FFMA.
#define FMA2(d, a, b) asm("fma.rn.f32x2 %0, %1, %2, %0;" : "+l"(d) : "l"(a), "l"(b))

// ---------------------------------------------------------------------------
// Fused SAGE linear: out[row] = (agg[row]/max(cnt,1)) @ Wl^T + b + X[row] @ Wr^T
// (optional ReLU).
//
// Both 128x128 weights live in smem TRANSPOSED with row stride 132 floats
// (33x16B -> 16B-aligned LDS.128, conflict-free reads). Each of 8 warps owns
// 8 rows; row values are staged in smem as duplicated interleaved float4
// {a,a,x,x} so each per-(row,k) broadcast is ONE LDS.128 (broadcast, 1 port
// cycle) feeding 8 packed FMAs. k staged in two halves.
// ---------------------------------------------------------------------------
template <bool RELU>
__global__ __launch_bounds__(256, 1) void gemm_kernel(
    const float* __restrict__ X,
    const float* __restrict__ Wl, const float* __restrict__ Wr,
    const float* __restrict__ bias, float* __restrict__ out, int N,
    int use_h_in, int use_h_out)
{
    const float* Xp = use_h_in ? reinterpret_cast<const float*>(g_h4) : X;
    float* op = use_h_out ? reinterpret_cast<float*>(g_h4) : out;
    const float* agg = reinterpret_cast<const float*>(g_agg4);

    extern __shared__ float smem[];
    float* s_wl = smem;                  // 128*132
    float* s_wr = smem + 128 * 132;      // 128*132
    float* s_b  = smem + 2 * 128 * 132;  // 128
    float* s_st = s_b + 128;             // 8 warps * 2048 floats

    int tid = threadIdx.x;
    for (int i = tid; i < 128 * 128; i += 256) {
        int n = i >> 7, k = i & 127;
        s_wl[k * 132 + n] = Wl[i];       // transpose: s_wl[k][n] = Wl[n][k]
        s_wr[k * 132 + n] = Wr[i];
    }
    if (tid < 128) s_b[tid] = bias[tid];
    __syncthreads();

    int warp = tid >> 5, lane = tid & 31;
    int lane4 = lane * 4;
    float* s_rw = s_st + warp * 2048;    // this warp's staging region

    unsigned long long b0 = *reinterpret_cast<const unsigned long long*>(s_b + lane4);
    unsigned long long b1 = *reinterpret_cast<const unsigned long long*>(s_b + lane4 + 2);

    for (int base = blockIdx.x * 64; base < N; base += gridDim.x * 64) {
        int row0 = base + warp * 8;
        unsigned long long acc[8][2];
        #pragma unroll
        for (int rr = 0; rr < 8; rr++) { acc[rr][0] = b0; acc[rr][1] = b1; }

        #pragma unroll
        for (int half = 0; half < 2; half++) {
            int kb = half * 64;
            __syncwarp();
            // ---- stage 8 rows x 64 k-values, duplicated {a,a,x,x} ----
            // lane owns local k = 2*lane, 2*lane+1; even k -> slot k/2,
            // odd k -> slot 32+k/2 (keeps STS.128 conflict-free).
            #pragma unroll
            for (int rr = 0; rr < 8; rr++) {
                int row = row0 + rr;
                if (row < N) {
                    float iv = 1.0f / fmaxf(g_cnt[row], 1.0f);
                    const float* arow = agg + (size_t)row * NF + kb;
                    const float* xrow = Xp + (size_t)row * NF + kb;
                    float2 av = *reinterpret_cast<const float2*>(arow + lane * 2);
                    float2 xv = *reinterpret_cast<const float2*>(xrow + lane * 2);
                    float a0 = av.x * iv, a1 = av.y * iv;
                    float4* rp = reinterpret_cast<float4*>(s_rw + rr * 256);
                    rp[lane]      = make_float4(a0, a0, xv.x, xv.x); // k = 2*lane
                    rp[32 + lane] = make_float4(a1, a1, xv.y, xv.y); // k = 2*lane+1
                }
            }
            __syncwarp();
            // ---- main loop: 2 k per step ----
            #pragma unroll 4
            for (int s = 0; s < 32; s++) {
                int k0 = kb + 2 * s;
                ulonglong2 WL0 = *reinterpret_cast<const ulonglong2*>(s_wl + k0 * 132 + lane4);
                ulonglong2 WR0 = *reinterpret_cast<const ulonglong2*>(s_wr + k0 * 132 + lane4);
                ulonglong2 WL1 = *reinterpret_cast<const ulonglong2*>(s_wl + (k0 + 1) * 132 + lane4);
                ulonglong2 WR1 = *reinterpret_cast<const ulonglong2*>(s_wr + (k0 + 1) * 132 + lane4);
                #pragma unroll
                for (int rr = 0; rr < 8; rr++) {
                    const ulonglong2* rp = reinterpret_cast<const ulonglong2*>(s_rw + rr * 256);
                    ulonglong2 AX0 = rp[s];        // {a(k0),a(k0), x(k0),x(k0)}
                    ulonglong2 AX1 = rp[32 + s];   // {a(k1),a(k1), x(k1),x(k1)}
                    FMA2(acc[rr][0], WL0.x, AX0.x);
                    FMA2(acc[rr][1], WL0.y, AX0.x);
                    FMA2(acc[rr][0], WR0.x, AX0.y);
                    FMA2(acc[rr][1], WR0.y, AX0.y);
                    FMA2(acc[rr][0], WL1.x, AX1.x);
                    FMA2(acc[rr][1], WL1.y, AX1.x);
                    FMA2(acc[rr][0], WR1.x, AX1.y);
                    FMA2(acc[rr][1], WR1.y, AX1.y);
                }
            }
        }
        // ---- epilogue ----
        #pragma unroll
        for (int rr = 0; rr < 8; rr++) {
            int row = row0 + rr;
            if (row < N) {
                float2 p0, p1;
                asm("mov.b64 {%0, %1}, %2;" : "=f"(p0.x), "=f"(p0.y) : "l"(acc[rr][0]));
                asm("mov.b64 {%0, %1}, %2;" : "=f"(p1.x), "=f"(p1.y) : "l"(acc[rr][1]));
                if (RELU) {
                    p0.x = fmaxf(p0.x, 0.f); p0.y = fmaxf(p0.y, 0.f);
                    p1.x = fmaxf(p1.x, 0.f); p1.y = fmaxf(p1.y, 0.f);
                }
                *reinterpret_cast<float4*>(op + (size_t)row * NF + lane4) =
                    make_float4(p0.x, p0.y, p1.x, p1.y);
            }
        }
    }
}

// ---------------------------------------------------------------------------
// Launch: detect -> zero -> scatter(+count) -> linear1(ReLU) -> zero ->
// scatter -> linear2.
// Input identification by EXACT element count:
//   12,800,000 -> x; 16,384 -> weights (appearance order w1_l, w1_r, w2_l,
//   w2_r); 128 -> biases (b1, b2); anything else -> edge_index (2*E elems).
// ---------------------------------------------------------------------------
extern "C" void kernel_launch(void* const* d_in, const int* in_sizes, int n_in,
                              void* d_out, int out_size) {
    const float* x = nullptr;
    const void* ei = nullptr;
    const float* w[4] = {nullptr, nullptr, nullptr, nullptr};
    const float* b[2] = {nullptr, nullptr};
    int nw = 0, nb = 0, E = 0, N = N_NODES;

    for (int i = 0; i < n_in; i++) {
        int sz = in_sizes[i];
        if (sz == N_NODES * NF) {            // x (12,800,000 floats)
            x = (const float*)d_in[i];
        } else if (sz == NF * NF) {          // weight matrices (16,384)
            if (nw < 4) w[nw++] = (const float*)d_in[i];
        } else if (sz == NF) {               // biases (128)
            if (nb < 2) b[nb++] = (const float*)d_in[i];
        } else {                             // edge_index (2*E elements)
            ei = d_in[i];
            E = sz / 2;
        }
    }
    const float *w1l = w[0], *w1r = w[1], *w2l = w[2], *w2r = w[3];
    const float *b1 = b[0], *b2 = b[1];
    float* out = (float*)d_out;

    size_t smem_bytes = (size_t)(2 * 128 * 132 + 128 + 8 * 2048) * sizeof(float); // ~196.5 KB
    cudaFuncSetAttribute(gemm_kernel<true>,  cudaFuncAttributeMaxDynamicSharedMemorySize, (int)smem_bytes);
    cudaFuncSetAttribute(gemm_kernel<false>, cudaFuncAttributeMaxDynamicSharedMemorySize, (int)smem_bytes);

    int n4 = N * NF / 4;
    int sc_grid = (E + 7) / 8;

    detect_kernel<<<1, 32>>>((const int*)ei);

    // Layer 1
    zero_kernel<<<(n4 + 255) / 256, 256>>>(n4, 1);
    if (sc_grid > 0) scatter_kernel<<<sc_grid, 256>>>(x, ei, E, 1, 0);
    gemm_kernel<true><<<148, 256, smem_bytes>>>(x, w1l, w1r, b1, out, N, 0, 1);

    // Layer 2 (counts reused: same edge set)
    zero_kernel<<<(n4 + 255) / 256, 256>>>(n4, 0);
    if (sc_grid > 0) scatter_kernel<<<sc_grid, 256>>>(x, ei, E, 0, 1);
    gemm_kernel<false><<<148, 256, smem_bytes>>>(x, w2l, w2r, b2, out, N, 1, 0);
}

// round 5
// speedup vs baseline: 1.3591x; 1.3591x over previous
#include <cuda_runtime.h>

#define NF 128
#define N_NODES 100000
#define E_MAX 2000000

// Scratch: static device globals (no runtime allocation allowed).
__device__ float4 g_agg4[(size_t)N_NODES * NF / 4];   // 51.2 MB mean-aggregated rows
__device__ float4 g_h4[(size_t)N_NODES * NF / 4];     // 51.2 MB hidden activations
__device__ int g_deg[N_NODES];                        // in-degree
__device__ int g_off[N_NODES];                        // CSR offsets (exclusive scan)
__device__ int g_cur[N_NODES];                        // fill cursors
__device__ int g_srcs[E_MAX];                         // src ids sorted by dst
__device__ int g_is64;                                // edge_index dtype flag

// ---------------------------------------------------------------------------
// Detect whether edge_index is int64 or int32 (harness may materialize the
// jnp.int64 reference input as int32). int64 of ids < 2^31 -> high words 0.
// ---------------------------------------------------------------------------
__global__ void detect_kernel(const int* __restrict__ ei_words) {
    if (threadIdx.x == 0 && blockIdx.x == 0) {
        int is64 = 1;
        #pragma unroll
        for (int k = 0; k < 64; k++)
            if (ei_words[2 * k + 1] != 0) { is64 = 0; break; }
        g_is64 = is64;
    }
}

__global__ void zero_deg_kernel() {
    int i = blockIdx.x * blockDim.x + threadIdx.x;
    if (i < N_NODES) g_deg[i] = 0;
}

__device__ __forceinline__ int load_edge(const void* ei, long long idx) {
    return g_is64 ? (int)((const long long*)ei)[idx] : ((const int*)ei)[idx];
}

// ---------------------------------------------------------------------------
// Histogram of destination in-degrees.
// ---------------------------------------------------------------------------
__global__ void hist_kernel(const void* __restrict__ ei, int E) {
    int e = blockIdx.x * blockDim.x + threadIdx.x;
    if (e >= E) return;
    int d = load_edge(ei, (long long)E + e);
    d = min(max(d, 0), N_NODES - 1);
    atomicAdd(&g_deg[d], 1);
}

// ---------------------------------------------------------------------------
// Single-block exclusive scan over g_deg -> g_off, g_cur. 1024 threads,
// warp shfl scans + cross-warp smem, sequential carry over 98 chunks.
// ---------------------------------------------------------------------------
__global__ void scan_kernel() {
    __shared__ int warp_sums[32];
    __shared__ int carry_s;
    int tid = threadIdx.x, lane = tid & 31, wid = tid >> 5;
    if (tid == 0) carry_s = 0;
    __syncthreads();
    for (int base = 0; base < N_NODES; base += 1024) {
        int i = base + tid;
        int v = (i < N_NODES) ? g_deg[i] : 0;
        int s = v;
        #pragma unroll
        for (int d = 1; d < 32; d <<= 1) {
            int t = __shfl_up_sync(0xFFFFFFFFu, s, d);
            if (lane >= d) s += t;
        }
        if (lane == 31) warp_sums[wid] = s;
        __syncthreads();
        if (wid == 0) {
            int ws = warp_sums[lane];
            #pragma unroll
            for (int d = 1; d < 32; d <<= 1) {
                int t = __shfl_up_sync(0xFFFFFFFFu, ws, d);
                if (lane >= d) ws += t;
            }
            warp_sums[lane] = ws;
        }
        __syncthreads();
        int warp_off = (wid == 0) ? 0 : warp_sums[wid - 1];
        int excl = carry_s + warp_off + s - v;
        if (i < N_NODES) { g_off[i] = excl; g_cur[i] = excl; }
        __syncthreads();
        if (tid == 0) carry_s += warp_sums[31];
        __syncthreads();
    }
}

// ---------------------------------------------------------------------------
// Scatter edges into dst-sorted src lists.
// ---------------------------------------------------------------------------
__global__ void fill_kernel(const void* __restrict__ ei, int E) {
    int e = blockIdx.x * blockDim.x + threadIdx.x;
    if (e >= E) return;
    int s = load_edge(ei, e);
    int d = load_edge(ei, (long long)E + e);
    s = min(max(s, 0), N_NODES - 1);
    d = min(max(d, 0), N_NODES - 1);
    int pos = atomicAdd(&g_cur[d], 1);
    if (pos >= 0 && pos < E_MAX) g_srcs[pos] = s;
}

// ---------------------------------------------------------------------------
// Gather-aggregate: one warp per node. Reads the node's sorted neighbor
// list, gathers each 512B source row (LDG.128 per lane, coalesced) and
// accumulates in registers (2 independent accumulators for MLP), then
// writes the MEAN once. No atomics, no zero pass, no count buffer.
// ---------------------------------------------------------------------------
__global__ __launch_bounds__(512) void aggregate_kernel(
    const float* __restrict__ feat, int use_h)
{
    const float4* f = use_h ? g_h4 : reinterpret_cast<const float4*>(feat);
    int w = (blockIdx.x * blockDim.x + threadIdx.x) >> 5;
    int lane = threadIdx.x & 31;
    if (w >= N_NODES) return;
    int off = g_off[w], deg = g_deg[w];
    float4 a0 = make_float4(0.f, 0.f, 0.f, 0.f);
    float4 a1 = make_float4(0.f, 0.f, 0.f, 0.f);
    for (int j0 = 0; j0 < deg; j0 += 32) {
        int nj = min(32, deg - j0);
        int my = (lane < nj) ? g_srcs[off + j0 + lane] : 0;
        int t = 0;
        for (; t + 2 <= nj; t += 2) {
            int s0 = __shfl_sync(0xFFFFFFFFu, my, t);
            int s1 = __shfl_sync(0xFFFFFFFFu, my, t + 1);
            float4 v0 = f[(size_t)s0 * 32 + lane];
            float4 v1 = f[(size_t)s1 * 32 + lane];
            a0.x += v0.x; a0.y += v0.y; a0.z += v0.z; a0.w += v0.w;
            a1.x += v1.x; a1.y += v1.y; a1.z += v1.z; a1.w += v1.w;
        }
        if (t < nj) {
            int s0 = __shfl_sync(0xFFFFFFFFu, my, t);
            float4 v0 = f[(size_t)s0 * 32 + lane];
            a0.x += v0.x; a0.y += v0.y; a0.z += v0.z; a0.w += v0.w;
        }
    }
    float iv = (deg > 0) ? 1.0f / (float)deg : 0.0f;
    float4 r;
    r.x = (a0.x + a1.x) * iv; r.y = (a0.y + a1.y) * iv;
    r.z = (a0.z + a1.z) * iv; r.w = (a0.w + a1.w) * iv;
    g_agg4[(size_t)w * 32 + lane] = r;
}

// Packed fp32x2 FMA (Blackwell): 2x the throughput of 3-reg FFMA.
#define FMA2(d, a, b) asm("fma.rn.f32x2 %0, %1, %2, %0;" : "+l"(d) : "l"(a), "l"(b))

// ---------------------------------------------------------------------------
// Fused SAGE linear: out[row] = agg_mean[row] @ Wl^T + b + X[row] @ Wr^T
// (optional ReLU). 512 threads (16 warps, 4/SMSP for latency hiding),
// 8 rows/warp, k staged in 32-wide chunks.
//
// Weights in smem TRANSPOSED, stride 128 (contiguous lane reads -> LDS.128
// conflict-free). Per-(row,k) inputs staged duplicated {a,a,x,x} so each
// broadcast is ONE LDS.128 feeding 4 packed FMA2. Per-SM per-k model:
// smem-port 256 cyc == FMA-pipe 256 cyc (balanced).
// ---------------------------------------------------------------------------
template <bool RELU>
__global__ __launch_bounds__(512, 1) void gemm_kernel(
    const float* __restrict__ X,
    const float* __restrict__ Wl, const float* __restrict__ Wr,
    const float* __restrict__ bias, float* __restrict__ out, int N,
    int use_h_in, int use_h_out)
{
    const float* Xp = use_h_in ? reinterpret_cast<const float*>(g_h4) : X;
    float* op = use_h_out ? reinterpret_cast<float*>(g_h4) : out;
    const float* agg = reinterpret_cast<const float*>(g_agg4);

    extern __shared__ float smem[];
    float* s_wl = smem;                   // 128*128
    float* s_wr = smem + 128 * 128;       // 128*128
    float* s_b  = smem + 2 * 128 * 128;   // 128
    float* s_st = s_b + 128;              // 16 warps * 1024 floats

    int tid = threadIdx.x;
    for (int i = tid; i < 128 * 128; i += 512) {
        int n = i >> 7, k = i & 127;
        s_wl[k * 128 + n] = Wl[i];        // s_wl[k][n] = Wl[n][k]
        s_wr[k * 128 + n] = Wr[i];
    }
    if (tid < 128) s_b[tid] = bias[tid];
    __syncthreads();

    int warp = tid >> 5, lane = tid & 31;
    int lane4 = lane * 4;
    float* s_rw = s_st + warp * 1024;     // 8 rows * 128 floats (32 k * 4)

    unsigned long long b0 = *reinterpret_cast<const unsigned long long*>(s_b + lane4);
    unsigned long long b1 = *reinterpret_cast<const unsigned long long*>(s_b + lane4 + 2);

    for (int base = blockIdx.x * 128; base < N; base += gridDim.x * 128) {
        int row0 = base + warp * 8;
        unsigned long long acc[8][2];
        #pragma unroll
        for (int rr = 0; rr < 8; rr++) { acc[rr][0] = b0; acc[rr][1] = b1; }

        #pragma unroll
        for (int chunk = 0; chunk < 4; chunk++) {
            int kb = chunk * 32;
            __syncwarp();
            // stage: lane <-> local k (32 lanes = 32 k). STS.128 contiguous.
            #pragma unroll
            for (int rr = 0; rr < 8; rr++) {
                int row = row0 + rr;
                if (row < N) {
                    float a  = agg[(size_t)row * NF + kb + lane];
                    float xx = Xp[(size_t)row * NF + kb + lane];
                    reinterpret_cast<float4*>(s_rw + rr * 128)[lane] =
                        make_float4(a, a, xx, xx);
                }
            }
            __syncwarp();
            #pragma unroll 2
            for (int k = 0; k < 32; k++) {
                const float* wk = s_wl + (kb + k) * 128 + lane4;
                ulonglong2 WL = *reinterpret_cast<const ulonglong2*>(wk);
                ulonglong2 WR = *reinterpret_cast<const ulonglong2*>(wk + 128 * 128);
                #pragma unroll
                for (int rr = 0; rr < 8; rr++) {
                    ulonglong2 AX = *reinterpret_cast<const ulonglong2*>(
                        s_rw + rr * 128 + k * 4);   // {a,a | x,x} broadcast
                    FMA2(acc[rr][0], WL.x, AX.x);
                    FMA2(acc[rr][1], WL.y, AX.x);
                    FMA2(acc[rr][0], WR.x, AX.y);
                    FMA2(acc[rr][1], WR.y, AX.y);
                }
            }
        }
        // epilogue
        #pragma unroll
        for (int rr = 0; rr < 8; rr++) {
            int row = row0 + rr;
            if (row < N) {
                float2 p0, p1;
                asm("mov.b64 {%0, %1}, %2;" : "=f"(p0.x), "=f"(p0.y) : "l"(acc[rr][0]));
                asm("mov.b64 {%0, %1}, %2;" : "=f"(p1.x), "=f"(p1.y) : "l"(acc[rr][1]));
                if (RELU) {
                    p0.x = fmaxf(p0.x, 0.f); p0.y = fmaxf(p0.y, 0.f);
                    p1.x = fmaxf(p1.x, 0.f); p1.y = fmaxf(p1.y, 0.f);
                }
                *reinterpret_cast<float4*>(op + (size_t)row * NF + lane4) =
                    make_float4(p0.x, p0.y, p1.x, p1.y);
            }
        }
    }
}

// ---------------------------------------------------------------------------
// detect -> hist -> scan -> fill -> agg1 -> gemm1(ReLU) -> agg2 -> gemm2
// Input identification by EXACT element count: 12.8M -> x; 16384 -> weights
// (w1_l, w1_r, w2_l, w2_r); 128 -> biases (b1, b2); else -> edge_index.
// ---------------------------------------------------------------------------
extern "C" void kernel_launch(void* const* d_in, const int* in_sizes, int n_in,
                              void* d_out, int out_size) {
    const float* x = nullptr;
    const void* ei = nullptr;
    const float* w[4] = {nullptr, nullptr, nullptr, nullptr};
    const float* b[2] = {nullptr, nullptr};
    int nw = 0, nb = 0, E = 0, N = N_NODES;

    for (int i = 0; i < n_in; i++) {
        int sz = in_sizes[i];
        if (sz == N_NODES * NF) {
            x = (const float*)d_in[i];
        } else if (sz == NF * NF) {
            if (nw < 4) w[nw++] = (const float*)d_in[i];
        } else if (sz == NF) {
            if (nb < 2) b[nb++] = (const float*)d_in[i];
        } else {
            ei = d_in[i];
            E = sz / 2;
        }
    }
    if (E > E_MAX) E = E_MAX;
    const float *w1l = w[0], *w1r = w[1], *w2l = w[2], *w2r = w[3];
    const float *b1 = b[0], *b2 = b[1];
    float* out = (float*)d_out;

    size_t smem_bytes = (size_t)(2 * 128 * 128 + 128 + 16 * 1024) * sizeof(float); // 197.1 KB
    cudaFuncSetAttribute(gemm_kernel<true>,  cudaFuncAttributeMaxDynamicSharedMemorySize, (int)smem_bytes);
    cudaFuncSetAttribute(gemm_kernel<false>, cudaFuncAttributeMaxDynamicSharedMemorySize, (int)smem_bytes);

    int agg_grid = (N_NODES * 32 + 511) / 512;   // one warp per node

    detect_kernel<<<1, 32>>>((const int*)ei);
    zero_deg_kernel<<<(N_NODES + 511) / 512, 512>>>();
    if (E > 0) {
        hist_kernel<<<(E + 511) / 512, 512>>>(ei, E);
        scan_kernel<<<1, 1024>>>();
        fill_kernel<<<(E + 511) / 512, 512>>>(ei, E);
    } else {
        scan_kernel<<<1, 1024>>>();
    }

    // Layer 1
    aggregate_kernel<<<agg_grid, 512>>>(x, 0);
    gemm_kernel<true><<<148, 512, smem_bytes>>>(x, w1l, w1r, b1, out, N, 0, 1);

    // Layer 2
    aggregate_kernel<<<agg_grid, 512>>>(x, 1);
    gemm_kernel<false><<<148, 512, smem_bytes>>>(x, w2l, w2r, b2, out, N, 1, 0);
}

// round 6
// speedup vs baseline: 1.5083x; 1.1098x over previous
#include <cuda_runtime.h>

#define NF 128
#define N_NODES 100000
#define E_MAX 2000000
#define SCAN_BLK 1024
#define SCAN_NBLK ((N_NODES + SCAN_BLK - 1) / SCAN_BLK)   // 98

// Scratch: static device globals (no runtime allocation allowed).
__device__ float4 g_agg4[(size_t)N_NODES * NF / 4];   // 51.2 MB mean-aggregated rows
__device__ float4 g_h4[(size_t)N_NODES * NF / 4];     // 51.2 MB hidden activations
__device__ int g_deg[N_NODES];                        // in-degree
__device__ int g_off[N_NODES];                        // CSR offsets (exclusive scan)
__device__ int g_cur[N_NODES];                        // fill cursors
__device__ int g_srcs[E_MAX];                         // src ids sorted by dst
__device__ int g_bsum[SCAN_NBLK];                     // per-block scan sums
__device__ int g_is64;                                // edge_index dtype flag

// ---------------------------------------------------------------------------
// Zero degrees + detect edge_index dtype (int64 of ids < 2^31 -> every high
// 4-byte word is 0; impossible for random int32 indices over 64 entries).
// ---------------------------------------------------------------------------
__global__ void init_kernel(const int* __restrict__ ei_words) {
    int i = blockIdx.x * blockDim.x + threadIdx.x;
    if (i < N_NODES) g_deg[i] = 0;
    if (i == 0) {
        int is64 = 1;
        #pragma unroll
        for (int k = 0; k < 64; k++)
            if (ei_words[2 * k + 1] != 0) { is64 = 0; break; }
        g_is64 = is64;
    }
}

__device__ __forceinline__ int load_edge(const void* ei, long long idx) {
    return g_is64 ? (int)((const long long*)ei)[idx] : ((const int*)ei)[idx];
}

// ---------------------------------------------------------------------------
// Histogram of destination in-degrees.
// ---------------------------------------------------------------------------
__global__ void hist_kernel(const void* __restrict__ ei, int E) {
    int e = blockIdx.x * blockDim.x + threadIdx.x;
    if (e >= E) return;
    int d = load_edge(ei, (long long)E + e);
    d = min(max(d, 0), N_NODES - 1);
    atomicAdd(&g_deg[d], 1);
}

// ---------------------------------------------------------------------------
// Multi-block exclusive scan, phase 1: each block scans its 1024-elem chunk
// (shfl warp scans + cross-warp smem), writes local exclusive prefix to
// g_off and the chunk total to g_bsum[blockIdx].
// ---------------------------------------------------------------------------
__global__ void scan1_kernel() {
    __shared__ int warp_sums[32];
    int tid = threadIdx.x, lane = tid & 31, wid = tid >> 5;
    int i = blockIdx.x * SCAN_BLK + tid;
    int v = (i < N_NODES) ? g_deg[i] : 0;
    int s = v;
    #pragma unroll
    for (int d = 1; d < 32; d <<= 1) {
        int t = __shfl_up_sync(0xFFFFFFFFu, s, d);
        if (lane >= d) s += t;
    }
    if (lane == 31) warp_sums[wid] = s;
    __syncthreads();
    if (wid == 0) {
        int ws = warp_sums[lane];
        #pragma unroll
        for (int d = 1; d < 32; d <<= 1) {
            int t = __shfl_up_sync(0xFFFFFFFFu, ws, d);
            if (lane >= d) ws += t;
        }
        warp_sums[lane] = ws;
    }
    __syncthreads();
    int warp_off = (wid == 0) ? 0 : warp_sums[wid - 1];
    if (i < N_NODES) g_off[i] = warp_off + s - v;       // block-local exclusive
    if (tid == SCAN_BLK - 1) g_bsum[blockIdx.x] = warp_off + s;
}

// Phase 2: one tiny block exclusive-scans the SCAN_NBLK block sums in place.
__global__ void scan2_kernel() {
    __shared__ int sh[SCAN_NBLK];
    int tid = threadIdx.x;
    if (tid < SCAN_NBLK) sh[tid] = g_bsum[tid];
    __syncthreads();
    if (tid == 0) {
        int run = 0;
        #pragma unroll 7
        for (int k = 0; k < SCAN_NBLK; k++) { int t = sh[k]; sh[k] = run; run += t; }
    }
    __syncthreads();
    if (tid < SCAN_NBLK) g_bsum[tid] = sh[tid];
}

// Phase 3: add block offsets, write final g_off and g_cur.
__global__ void scan3_kernel() {
    int i = blockIdx.x * SCAN_BLK + threadIdx.x;
    if (i < N_NODES) {
        int o = g_off[i] + g_bsum[blockIdx.x];
        g_off[i] = o;
        g_cur[i] = o;
    }
}

// ---------------------------------------------------------------------------
// Scatter edges into dst-sorted src lists.
// ---------------------------------------------------------------------------
__global__ void fill_kernel(const void* __restrict__ ei, int E) {
    int e = blockIdx.x * blockDim.x + threadIdx.x;
    if (e >= E) return;
    int s = load_edge(ei, e);
    int d = load_edge(ei, (long long)E + e);
    s = min(max(s, 0), N_NODES - 1);
    d = min(max(d, 0), N_NODES - 1);
    int pos = atomicAdd(&g_cur[d], 1);
    if (pos >= 0 && pos < E_MAX) g_srcs[pos] = s;
}

// ---------------------------------------------------------------------------
// Gather-aggregate: one warp per node. Reads the node's sorted neighbor
// list, gathers each 512B source row (LDG.128 per lane, coalesced) and
// accumulates in registers, then writes the MEAN once. No atomics.
// ---------------------------------------------------------------------------
__global__ __launch_bounds__(512) void aggregate_kernel(
    const float* __restrict__ feat, int use_h)
{
    const float4* f = use_h ? g_h4 : reinterpret_cast<const float4*>(feat);
    int w = (blockIdx.x * blockDim.x + threadIdx.x) >> 5;
    int lane = threadIdx.x & 31;
    if (w >= N_NODES) return;
    int off = g_off[w], deg = g_deg[w];
    float4 a0 = make_float4(0.f, 0.f, 0.f, 0.f);
    float4 a1 = make_float4(0.f, 0.f, 0.f, 0.f);
    for (int j0 = 0; j0 < deg; j0 += 32) {
        int nj = min(32, deg - j0);
        int my = (lane < nj) ? g_srcs[off + j0 + lane] : 0;
        int t = 0;
        for (; t + 2 <= nj; t += 2) {
            int s0 = __shfl_sync(0xFFFFFFFFu, my, t);
            int s1 = __shfl_sync(0xFFFFFFFFu, my, t + 1);
            float4 v0 = f[(size_t)s0 * 32 + lane];
            float4 v1 = f[(size_t)s1 * 32 + lane];
            a0.x += v0.x; a0.y += v0.y; a0.z += v0.z; a0.w += v0.w;
            a1.x += v1.x; a1.y += v1.y; a1.z += v1.z; a1.w += v1.w;
        }
        if (t < nj) {
            int s0 = __shfl_sync(0xFFFFFFFFu, my, t);
            float4 v0 = f[(size_t)s0 * 32 + lane];
            a0.x += v0.x; a0.y += v0.y; a0.z += v0.z; a0.w += v0.w;
        }
    }
    float iv = (deg > 0) ? 1.0f / (float)deg : 0.0f;
    float4 r;
    r.x = (a0.x + a1.x) * iv; r.y = (a0.y + a1.y) * iv;
    r.z = (a0.z + a1.z) * iv; r.w = (a0.w + a1.w) * iv;
    g_agg4[(size_t)w * 32 + lane] = r;
}

// Packed fp32x2 FMA (Blackwell): 2x the throughput of 3-reg FFMA.
#define FMA2(d, a, b) asm("fma.rn.f32x2 %0, %1, %2, %0;" : "+l"(d) : "l"(a), "l"(b))

// ---------------------------------------------------------------------------
// Fused SAGE linear: out[row] = agg_mean[row] @ Wl^T + b + X[row] @ Wr^T
// (optional ReLU). 512 threads (16 warps, 4/SMSP), 8 rows/warp, k staged in
// 32-wide chunks. Weights in smem TRANSPOSED, stride 128; per-(row,k) inputs
// staged duplicated {a,a,x,x} so each broadcast is ONE LDS.128 feeding 4
// packed FMA2 (smem-port cyc == FMA-pipe cyc, balanced).
// ---------------------------------------------------------------------------
template <bool RELU>
__global__ __launch_bounds__(512, 1) void gemm_kernel(
    const float* __restrict__ X,
    const float* __restrict__ Wl, const float* __restrict__ Wr,
    const float* __restrict__ bias, float* __restrict__ out, int N,
    int use_h_in, int use_h_out)
{
    const float* Xp = use_h_in ? reinterpret_cast<const float*>(g_h4) : X;
    float* op = use_h_out ? reinterpret_cast<float*>(g_h4) : out;
    const float* agg = reinterpret_cast<const float*>(g_agg4);

    extern __shared__ float smem[];
    float* s_wl = smem;                   // 128*128
    float* s_wr = smem + 128 * 128;       // 128*128
    float* s_b  = smem + 2 * 128 * 128;   // 128
    float* s_st = s_b + 128;              // 16 warps * 1024 floats

    int tid = threadIdx.x;
    for (int i = tid; i < 128 * 128; i += 512) {
        int n = i >> 7, k = i & 127;
        s_wl[k * 128 + n] = Wl[i];        // s_wl[k][n] = Wl[n][k]
        s_wr[k * 128 + n] = Wr[i];
    }
    if (tid < 128) s_b[tid] = bias[tid];
    __syncthreads();

    int warp = tid >> 5, lane = tid & 31;
    int lane4 = lane * 4;
    float* s_rw = s_st + warp * 1024;     // 8 rows * 128 floats (32 k * 4)

    unsigned long long b0 = *reinterpret_cast<const unsigned long long*>(s_b + lane4);
    unsigned long long b1 = *reinterpret_cast<const unsigned long long*>(s_b + lane4 + 2);

    for (int base = blockIdx.x * 128; base < N; base += gridDim.x * 128) {
        int row0 = base + warp * 8;
        unsigned long long acc[8][2];
        #pragma unroll
        for (int rr = 0; rr < 8; rr++) { acc[rr][0] = b0; acc[rr][1] = b1; }

        #pragma unroll
        for (int chunk = 0; chunk < 4; chunk++) {
            int kb = chunk * 32;
            __syncwarp();
            #pragma unroll
            for (int rr = 0; rr < 8; rr++) {
                int row = row0 + rr;
                if (row < N) {
                    float a  = agg[(size_t)row * NF + kb + lane];
                    float xx = Xp[(size_t)row * NF + kb + lane];
                    reinterpret_cast<float4*>(s_rw + rr * 128)[lane] =
                        make_float4(a, a, xx, xx);
                }
            }
            __syncwarp();
            #pragma unroll 2
            for (int k = 0; k < 32; k++) {
                const float* wk = s_wl + (kb + k) * 128 + lane4;
                ulonglong2 WL = *reinterpret_cast<const ulonglong2*>(wk);
                ulonglong2 WR = *reinterpret_cast<const ulonglong2*>(wk + 128 * 128);
                #pragma unroll
                for (int rr = 0; rr < 8; rr++) {
                    ulonglong2 AX = *reinterpret_cast<const ulonglong2*>(
                        s_rw + rr * 128 + k * 4);   // {a,a | x,x} broadcast
                    FMA2(acc[rr][0], WL.x, AX.x);
                    FMA2(acc[rr][1], WL.y, AX.x);
                    FMA2(acc[rr][0], WR.x, AX.y);
                    FMA2(acc[rr][1], WR.y, AX.y);
                }
            }
        }
        #pragma unroll
        for (int rr = 0; rr < 8; rr++) {
            int row = row0 + rr;
            if (row < N) {
                float2 p0, p1;
                asm("mov.b64 {%0, %1}, %2;" : "=f"(p0.x), "=f"(p0.y) : "l"(acc[rr][0]));
                asm("mov.b64 {%0, %1}, %2;" : "=f"(p1.x), "=f"(p1.y) : "l"(acc[rr][1]));
                if (RELU) {
                    p0.x = fmaxf(p0.x, 0.f); p0.y = fmaxf(p0.y, 0.f);
                    p1.x = fmaxf(p1.x, 0.f); p1.y = fmaxf(p1.y, 0.f);
                }
                *reinterpret_cast<float4*>(op + (size_t)row * NF + lane4) =
                    make_float4(p0.x, p0.y, p1.x, p1.y);
            }
        }
    }
}

// ---------------------------------------------------------------------------
// init -> hist -> scan1/2/3 -> fill -> agg1 -> gemm1(ReLU) -> agg2 -> gemm2
// Input identification by EXACT element count: 12.8M -> x; 16384 -> weights
// (w1_l, w1_r, w2_l, w2_r); 128 -> biases (b1, b2); else -> edge_index.
// ---------------------------------------------------------------------------
extern "C" void kernel_launch(void* const* d_in, const int* in_sizes, int n_in,
                              void* d_out, int out_size) {
    const float* x = nullptr;
    const void* ei = nullptr;
    const float* w[4] = {nullptr, nullptr, nullptr, nullptr};
    const float* b[2] = {nullptr, nullptr};
    int nw = 0, nb = 0, E = 0, N = N_NODES;

    for (int i = 0; i < n_in; i++) {
        int sz = in_sizes[i];
        if (sz == N_NODES * NF) {
            x = (const float*)d_in[i];
        } else if (sz == NF * NF) {
            if (nw < 4) w[nw++] = (const float*)d_in[i];
        } else if (sz == NF) {
            if (nb < 2) b[nb++] = (const float*)d_in[i];
        } else {
            ei = d_in[i];
            E = sz / 2;
        }
    }
    if (E > E_MAX) E = E_MAX;
    const float *w1l = w[0], *w1r = w[1], *w2l = w[2], *w2r = w[3];
    const float *b1 = b[0], *b2 = b[1];
    float* out = (float*)d_out;

    size_t smem_bytes = (size_t)(2 * 128 * 128 + 128 + 16 * 1024) * sizeof(float); // 197.1 KB
    cudaFuncSetAttribute(gemm_kernel<true>,  cudaFuncAttributeMaxDynamicSharedMemorySize, (int)smem_bytes);
    cudaFuncSetAttribute(gemm_kernel<false>, cudaFuncAttributeMaxDynamicSharedMemorySize, (int)smem_bytes);

    int agg_grid = (N_NODES * 32 + 511) / 512;   // one warp per node

    init_kernel<<<(N_NODES + 511) / 512, 512>>>((const int*)ei);
    if (E > 0) hist_kernel<<<(E + 511) / 512, 512>>>(ei, E);
    scan1_kernel<<<SCAN_NBLK, SCAN_BLK>>>();
    scan2_kernel<<<1, 128>>>();
    scan3_kernel<<<SCAN_NBLK, SCAN_BLK>>>();
    if (E > 0) fill_kernel<<<(E + 511) / 512, 512>>>(ei, E);

    // Layer 1
    aggregate_kernel<<<agg_grid, 512>>>(x, 0);
    gemm_kernel<true><<<148, 512, smem_bytes>>>(x, w1l, w1r, b1, out, N, 0, 1);

    // Layer 2
    aggregate_kernel<<<agg_grid, 512>>>(x, 1);
    gemm_kernel<false><<<148, 512, smem_bytes>>>(x, w2l, w2r, b2, out, N, 1, 0);
}